// round 7
// baseline (speedup 1.0000x reference)
#include <cuda_runtime.h>

#define LOG2E 1.4426950408889634f
#define EPS   1e-8f

__device__ float        g_num[2][8192];   // per-row k-parity partial numerators
__device__ float        g_idl[8192];      // per-row ideal DCG
__device__ unsigned int g_done;           // zero-init; last block resets (replay safe)

__device__ __forceinline__ float ex2a(float x) {
    float r; asm("ex2.approx.ftz.f32 %0, %1;" : "=f"(r) : "f"(x)); return r;
}
__device__ __forceinline__ float lg2a(float x) {
    float r; asm("lg2.approx.ftz.f32 %0, %1;" : "=f"(r) : "f"(x)); return r;
}

// Folded both-orders contribution of one unordered pair.
// si is score*log2e; a = |si - sj| in log2 units:
//   term = |gi-gj| * (a + 2*log2(1 + 2^{-a}))   (accumulated negatively)
__device__ __forceinline__ float pair_term(float si, float gi, float2 p) {
    const float a = fabsf(si - p.x);
    const float u = ex2a(-a);                 // MUFU.EX2
    const float l = lg2a(1.0f + u);           // MUFU.LG2
    return fabsf(gi - p.y) * fmaf(2.0f, l, a);
}

// Two blocks per row: row = bid>>1, parity h = bid&1 takes k = 1+h, 3+h, ...
// Row staged in smem as (score*log2e, gain), first 64 entries mirrored past L
// so partner index i+k never wraps.
__global__ void __launch_bounds__(128) ndcg_kernel(
    const float* __restrict__ scores,
    const int*   __restrict__ relev,
    const int*   __restrict__ qlen,
    float*       __restrict__ out,
    int D, int B)
{
    const int bid = blockIdx.x;
    const int b   = bid >> 1;          // row
    const int h   = bid & 1;           // k-parity group
    const int i   = threadIdx.x;       // 0..127 = D

    __shared__ float2 s_sg[192];
    __shared__ int    s_cnt[8];
    __shared__ float  s_red[4];
    __shared__ int    s_last;

    const int  L     = qlen[b];
    const bool valid = (i < L);

    const float sv = scores[b * D + i] * LOG2E;
    const int   rv = relev[b * D + i];
    const float gv = valid ? (float)((1 << rv) - 1) : 0.0f;   // 2^rel - 1

    s_sg[i] = make_float2(sv, gv);
    if (h == 0 && i < 8) s_cnt[i] = 0;
    __syncthreads();

    if (h == 0 && valid) atomicAdd(&s_cnt[rv], 1);
    if (i < 64) s_sg[L + i] = s_sg[i];   // mirror (reads reach at most L-1+63)
    __syncthreads();

    // ---- this group's share of the pairwise sum ----
    float n0 = 0.0f, n1 = 0.0f, n2 = 0.0f, n3 = 0.0f;
    if (valid && L > 1) {
        const int     halfm = (L - 1) >> 1;
        const float2* base  = &s_sg[i];

        int k = 1 + h;
        for (; k + 6 <= halfm; k += 8) {            // 4 pairs/trip, stride 2
            n0 -= pair_term(sv, gv, base[k]);
            n1 -= pair_term(sv, gv, base[k + 2]);
            n2 -= pair_term(sv, gv, base[k + 4]);
            n3 -= pair_term(sv, gv, base[k + 6]);
        }
        for (; k <= halfm; k += 2)
            n0 -= pair_term(sv, gv, base[k]);

        // tie distance k=L/2 (L even): counted once, by group 1, i < L/2
        if ((h == 1) && ((L & 1) == 0) && (i < (L >> 1)))
            n1 -= pair_term(sv, gv, s_sg[i + (L >> 1)]);
    }
    float num = (n0 + n1) + (n2 + n3);

    // ---- ideal DCG via counting sort (group 0 only; gains in {0,1,3,7,15}) ----
    float idl = 0.0f;
    if (h == 0 && valid) {
        const int c4 = s_cnt[4];
        const int c3 = c4 + s_cnt[3];
        const int c2 = c3 + s_cnt[2];
        const int c1 = c2 + s_cnt[1];
        float gr;
        if      (i < c4) gr = 15.0f;
        else if (i < c3) gr = 7.0f;
        else if (i < c2) gr = 3.0f;
        else if (i < c1) gr = 1.0f;
        else             gr = 0.0f;
        idl = __fdividef(gr, lg2a((float)(i + 2)));
    }

    // ---- block reduction ----
    #pragma unroll
    for (int off = 16; off > 0; off >>= 1) {
        num += __shfl_down_sync(0xFFFFFFFFu, num, off);
        idl += __shfl_down_sync(0xFFFFFFFFu, idl, off);
    }
    const int wid  = i >> 5;
    const int lane = i & 31;
    __shared__ float s_rn[4], s_ri[4];
    if (lane == 0) { s_rn[wid] = num; s_ri[wid] = idl; }
    __syncthreads();
    if (i == 0) {
        g_num[h][b] = (s_rn[0] + s_rn[1]) + (s_rn[2] + s_rn[3]);
        if (h == 0) g_idl[b] = (s_ri[0] + s_ri[1]) + (s_ri[2] + s_ri[3]);
        __threadfence();
        const unsigned int t = atomicAdd(&g_done, 1u);
        s_last = (t == (unsigned int)(gridDim.x - 1));
    }
    __syncthreads();

    // ---- last block: deterministic final reduction over all rows ----
    if (s_last) {
        __threadfence();
        float s = 0.0f;
        for (int r = i; r < B; r += 128) {
            const float n  = g_num[0][r] + g_num[1][r];
            s += __fdividef(-n, g_idl[r] + EPS);
        }
        #pragma unroll
        for (int off = 16; off > 0; off >>= 1)
            s += __shfl_down_sync(0xFFFFFFFFu, s, off);
        if (lane == 0) s_red[wid] = s;
        __syncthreads();
        if (i == 0) {
            out[0] = ((s_red[0] + s_red[1]) + (s_red[2] + s_red[3])) / (float)B;
            g_done = 0;   // reset for next graph replay
        }
    }
}

extern "C" void kernel_launch(void* const* d_in, const int* in_sizes, int n_in,
                              void* d_out, int out_size)
{
    const float* scores = (const float*)d_in[0];
    const int*   relev  = (const int*)  d_in[1];
    const int*   qlen   = (const int*)  d_in[2];
    float*       out    = (float*)      d_out;

    const int B = in_sizes[2];
    const int D = in_sizes[0] / B;   // 128

    ndcg_kernel<<<2 * B, 128>>>(scores, relev, qlen, out, D, B);
}

// round 8
// speedup vs baseline: 1.1029x; 1.1029x over previous
#include <cuda_runtime.h>

#define LOG2E 1.4426950408889634f
#define EPS   1e-8f

__device__ float        g_partials[8192];
__device__ unsigned int g_done;   // zero-init; last block resets -> graph-replay safe

__device__ __forceinline__ float ex2a(float x) {
    float r; asm("ex2.approx.ftz.f32 %0, %1;" : "=f"(r) : "f"(x)); return r;
}
__device__ __forceinline__ float lg2a(float x) {
    float r; asm("lg2.approx.ftz.f32 %0, %1;" : "=f"(r) : "f"(x)); return r;
}

// One unordered pair, both orders folded. si is score*log2e.
// nm = -|si-sj|;  term = |gi-gj| * (-nm + 2*log2(1 + 2^{nm}))
__device__ __forceinline__ float pair_term(float si, float gi, float2 p) {
    const float d  = si - p.x;
    const float nm = 0.0f - fabsf(d);          // FADD -|d|
    const float u  = ex2a(nm);                 // MUFU.EX2
    const float l  = lg2a(1.0f + u);           // MUFU.LG2
    const float q  = fmaf(2.0f, l, -nm);       // free neg modifier
    return fabsf(gi - p.y) * q;
}

// Block-per-row, 128 threads. Row staged in smem as (score*log2e, gain) with
// the first 64 entries mirrored past L so partner index i+k never wraps.
__global__ void __launch_bounds__(128) ndcg_kernel(
    const float* __restrict__ scores,
    const int*   __restrict__ relev,
    const int*   __restrict__ qlen,
    float*       __restrict__ out,
    int D, int B)
{
    const int b = blockIdx.x;
    const int i = threadIdx.x;          // 0..127 = D

    __shared__ float2 s_sg[192];
    __shared__ int    s_cnt[8];
    __shared__ float  s_rn[4], s_ri[4];
    __shared__ int    s_last;

    const int  L     = qlen[b];
    const bool valid = (i < L);

    const float sv = scores[b * D + i] * LOG2E;
    const int   rv = relev[b * D + i];
    const float gv = valid ? (float)((1 << rv) - 1) : 0.0f;   // 2^rel - 1

    s_sg[i] = make_float2(sv, gv);
    if (i < 8) s_cnt[i] = 0;
    __syncthreads();

    if (valid) atomicAdd(&s_cnt[rv], 1);
    if (i < 64) s_sg[L + i] = s_sg[i];   // mirror: loop reads reach <= L-1+63
    __syncthreads();

    // ---- pairwise sum, cyclic-distance enumeration, 4 independent chains ----
    float n0 = 0.0f, n1 = 0.0f, n2 = 0.0f, n3 = 0.0f;
    if (valid && L > 1) {
        const int     halfm = (L - 1) >> 1;
        const float2* base  = &s_sg[i];

        int k = 1;
        for (; k + 3 <= halfm; k += 4) {
            n0 -= pair_term(sv, gv, base[k]);
            n1 -= pair_term(sv, gv, base[k + 1]);
            n2 -= pair_term(sv, gv, base[k + 2]);
            n3 -= pair_term(sv, gv, base[k + 3]);
        }
        for (; k <= halfm; ++k)
            n0 -= pair_term(sv, gv, base[k]);

        // tie distance k=L/2 (L even): counted once, by i < L/2 (no wrap)
        if (((L & 1) == 0) && (i < (L >> 1)))
            n1 -= pair_term(sv, gv, s_sg[i + (L >> 1)]);
    }
    float num = (n0 + n1) + (n2 + n3);

    // ---- ideal DCG via counting sort (gains in {0,1,3,7,15}) ----
    float idl = 0.0f;
    if (valid) {
        const int c4 = s_cnt[4];
        const int c3 = c4 + s_cnt[3];
        const int c2 = c3 + s_cnt[2];
        const int c1 = c2 + s_cnt[1];
        float gr;
        if      (i < c4) gr = 15.0f;
        else if (i < c3) gr = 7.0f;
        else if (i < c2) gr = 3.0f;
        else if (i < c1) gr = 1.0f;
        else             gr = 0.0f;
        idl = __fdividef(gr, lg2a((float)(i + 2)));
    }

    // ---- block reduction of (num, idl) ----
    #pragma unroll
    for (int off = 16; off > 0; off >>= 1) {
        num += __shfl_down_sync(0xFFFFFFFFu, num, off);
        idl += __shfl_down_sync(0xFFFFFFFFu, idl, off);
    }
    const int wid  = i >> 5;
    const int lane = i & 31;
    if (lane == 0) { s_rn[wid] = num; s_ri[wid] = idl; }
    __syncthreads();
    if (i == 0) {
        const float n  = (s_rn[0] + s_rn[1]) + (s_rn[2] + s_rn[3]);
        const float id = (s_ri[0] + s_ri[1]) + (s_ri[2] + s_ri[3]);
        g_partials[b] = -n / (id + EPS);
        __threadfence();
        const unsigned int t = atomicAdd(&g_done, 1u);
        s_last = (t == (unsigned int)(gridDim.x - 1));
    }
    __syncthreads();

    // ---- last block: deterministic final reduction ----
    if (s_last) {
        __threadfence();
        float s = 0.0f;
        for (int r = i; r < B; r += 128) s += g_partials[r];
        #pragma unroll
        for (int off = 16; off > 0; off >>= 1)
            s += __shfl_down_sync(0xFFFFFFFFu, s, off);
        if (lane == 0) s_rn[wid] = s;
        __syncthreads();
        if (i == 0) {
            out[0] = ((s_rn[0] + s_rn[1]) + (s_rn[2] + s_rn[3])) / (float)B;
            g_done = 0;   // reset for next graph replay
        }
    }
}

extern "C" void kernel_launch(void* const* d_in, const int* in_sizes, int n_in,
                              void* d_out, int out_size)
{
    const float* scores = (const float*)d_in[0];
    const int*   relev  = (const int*)  d_in[1];
    const int*   qlen   = (const int*)  d_in[2];
    float*       out    = (float*)      d_out;

    const int B = in_sizes[2];
    const int D = in_sizes[0] / B;   // 128

    ndcg_kernel<<<B, 128>>>(scores, relev, qlen, out, D, B);
}

// round 9
// speedup vs baseline: 1.1250x; 1.0200x over previous
#include <cuda_runtime.h>

#define LOG2E 1.4426950408889634f
#define EPS   1e-8f

__device__ float        g_partials[8192];
__device__ unsigned int g_done;   // zero-init; last CTA resets -> graph-replay safe

__device__ __forceinline__ float ex2a(float x) {
    float r; asm("ex2.approx.ftz.f32 %0, %1;" : "=f"(r) : "f"(x)); return r;
}
__device__ __forceinline__ float lg2a(float x) {
    float r; asm("lg2.approx.ftz.f32 %0, %1;" : "=f"(r) : "f"(x)); return r;
}

// One unordered pair, both orders folded. si is score*log2e.
// nm = -|si-sj|;  term = |gi-gj| * (-nm + 2*log2(1 + 2^{nm}))
__device__ __forceinline__ float pair_term(float si, float gi, float2 p) {
    const float d  = si - p.x;
    const float nm = 0.0f - fabsf(d);
    const float u  = ex2a(nm);                 // MUFU.EX2
    const float l  = lg2a(1.0f + u);           // MUFU.LG2
    const float q  = fmaf(2.0f, l, -nm);
    return fabsf(gi - p.y) * q;
}

// 256 threads = two independent 128-thread row-groups; 2 rows per CTA.
// Row staged in smem as (score*log2e, gain); thread i<64 also writes the
// mirror slot L+i from its own register, so partner index i+k never wraps
// and only ONE barrier is needed before the loop.
__global__ void __launch_bounds__(256) ndcg_kernel(
    const float* __restrict__ scores,
    const int*   __restrict__ relev,
    const int*   __restrict__ qlen,
    float*       __restrict__ out,
    int D, int B)
{
    const int tid = threadIdx.x;
    const int g   = tid >> 7;                 // row-group 0/1
    const int i   = tid & 127;                // doc index
    const int row = blockIdx.x * 2 + g;

    __shared__ float2 s_sg[2][192];
    __shared__ int    s_cnt[2][8];
    __shared__ float  s_rn[2][4], s_ri[2][4];
    __shared__ int    s_last;

    float num = 0.0f, idl = 0.0f;
    int   L   = 0;
    bool  row_ok = (row < B);

    float sv = 0.0f, gv = 0.0f;
    if (row_ok) {
        L = qlen[row];
        const bool valid = (i < L);

        sv = scores[row * D + i] * LOG2E;
        const int rv = relev[row * D + i];
        gv = valid ? (float)((1 << rv) - 1) : 0.0f;   // 2^rel - 1

        if (i < 8) s_cnt[g][i] = 0;
        // primary slot: ONLY valid threads write (slots >= L belong to mirror)
        if (valid) s_sg[g][i] = make_float2(sv, gv);
        // mirror: thread i<64 writes its own value at L+i (no sync needed)
        if (i < 64) s_sg[g][L + i] = make_float2(sv, i < L ? gv : 0.0f);
    }
    __syncthreads();
    if (row_ok && i < L) atomicAdd(&s_cnt[g][relev[row * D + i] & 7], 1);
    __syncthreads();

    if (row_ok && i < L) {
        // ---- pairwise sum, cyclic-distance enumeration, 4 chains ----
        if (L > 1) {
            const int     halfm = (L - 1) >> 1;
            const float2* base  = &s_sg[g][i];
            float n0 = 0.0f, n1 = 0.0f, n2 = 0.0f, n3 = 0.0f;

            int k = 1;
            for (; k + 3 <= halfm; k += 4) {
                n0 -= pair_term(sv, gv, base[k]);
                n1 -= pair_term(sv, gv, base[k + 1]);
                n2 -= pair_term(sv, gv, base[k + 2]);
                n3 -= pair_term(sv, gv, base[k + 3]);
            }
            for (; k <= halfm; ++k)
                n0 -= pair_term(sv, gv, base[k]);

            // tie distance k=L/2 (L even): counted once, by i < L/2
            if (((L & 1) == 0) && (i < (L >> 1)))
                n1 -= pair_term(sv, gv, s_sg[g][i + (L >> 1)]);

            num = (n0 + n1) + (n2 + n3);
        }

        // ---- ideal DCG via counting sort (gains in {0,1,3,7,15}) ----
        const int c4 = s_cnt[g][4];
        const int c3 = c4 + s_cnt[g][3];
        const int c2 = c3 + s_cnt[g][2];
        const int c1 = c2 + s_cnt[g][1];
        float gr;
        if      (i < c4) gr = 15.0f;
        else if (i < c3) gr = 7.0f;
        else if (i < c2) gr = 3.0f;
        else if (i < c1) gr = 1.0f;
        else             gr = 0.0f;
        idl = __fdividef(gr, lg2a((float)(i + 2)));
    }

    // ---- group reduction of (num, idl) ----
    #pragma unroll
    for (int off = 16; off > 0; off >>= 1) {
        num += __shfl_down_sync(0xFFFFFFFFu, num, off);
        idl += __shfl_down_sync(0xFFFFFFFFu, idl, off);
    }
    const int wg   = (tid >> 5) & 3;          // warp within group
    const int lane = tid & 31;
    if (lane == 0) { s_rn[g][wg] = num; s_ri[g][wg] = idl; }
    __syncthreads();
    if (i == 0 && row_ok) {
        const float n  = (s_rn[g][0] + s_rn[g][1]) + (s_rn[g][2] + s_rn[g][3]);
        const float id = (s_ri[g][0] + s_ri[g][1]) + (s_ri[g][2] + s_ri[g][3]);
        g_partials[row] = -n / (id + EPS);
    }
    __syncthreads();
    if (tid == 0) {
        __threadfence();
        const unsigned int t = atomicAdd(&g_done, 1u);
        s_last = (t == (unsigned int)(gridDim.x - 1));
    }
    __syncthreads();

    // ---- last CTA: deterministic final reduction ----
    if (s_last) {
        __threadfence();
        float s = 0.0f;
        for (int r = tid; r < B; r += 256) s += g_partials[r];
        #pragma unroll
        for (int off = 16; off > 0; off >>= 1)
            s += __shfl_down_sync(0xFFFFFFFFu, s, off);
        const int w8 = tid >> 5;
        __shared__ float s_fin[8];
        if (lane == 0) s_fin[w8] = s;
        __syncthreads();
        if (tid == 0) {
            float t = 0.0f;
            #pragma unroll
            for (int w = 0; w < 8; ++w) t += s_fin[w];
            out[0] = t / (float)B;
            g_done = 0;   // reset for next graph replay
        }
    }
}

extern "C" void kernel_launch(void* const* d_in, const int* in_sizes, int n_in,
                              void* d_out, int out_size)
{
    const float* scores = (const float*)d_in[0];
    const int*   relev  = (const int*)  d_in[1];
    const int*   qlen   = (const int*)  d_in[2];
    float*       out    = (float*)      d_out;

    const int B = in_sizes[2];
    const int D = in_sizes[0] / B;   // 128

    const int blocks = (B + 1) / 2;
    ndcg_kernel<<<blocks, 256>>>(scores, relev, qlen, out, D, B);
}